// round 3
// baseline (speedup 1.0000x reference)
#include <cuda_runtime.h>
#include <cstdint>

// ---------------- problem constants ----------------
#define HGT 300
#define WID 400
#define NPIX (HGT * WID)
#define BX0 (-20.0f)
#define BX1 (20.0f)
#define BY0 (-10.0f)
#define BY1 (30.0f)
#define BZ0 (-3.0f)
#define BZ1 (4.0f)
#define BRES (0.1f)
#define KSAMP 512

// ---------------- scratch (no allocs allowed) ----------------
__device__ unsigned int       g_zmax[NPIX];   // order-preserving float encoding of max z
__device__ unsigned long long g_ic[NPIX];     // [63:40]=count, [39:0]=intensity sum in 16.16 fx

// order-preserving float<->uint map (monotone: f1<f2 <=> enc(f1)<enc(f2))
__device__ __forceinline__ unsigned int enc_f(float f) {
    unsigned int b = __float_as_uint(f);
    return (b & 0x80000000u) ? ~b : (b | 0x80000000u);
}
__device__ __forceinline__ float dec_f(unsigned int u) {
    unsigned int b = (u & 0x80000000u) ? (u ^ 0x80000000u) : ~u;
    return __uint_as_float(b);
}

// ---------------- kernels ----------------
__global__ void init_kernel(float* __restrict__ out) {
    int i = blockIdx.x * blockDim.x + threadIdx.x;
    int stride = gridDim.x * blockDim.x;
    for (int j = i; j < NPIX; j += stride) {
        g_zmax[j] = 0u;            // any real z encodes > 0; gated by count anyway
        g_ic[j]   = 0ull;
        out[3 * NPIX + j] = 0.0f;  // trajectory channel
        out[4 * NPIX + j] = 0.0f;  // map channel
    }
}

__global__ void lidar_kernel(const float4* __restrict__ pts, int n) {
    int i = blockIdx.x * blockDim.x + threadIdx.x;
    if (i >= n) return;
    float4 p = pts[i];
    // mask exactly as reference (on raw coords)
    if (p.x >= BX0 && p.x < BX1 && p.y >= BY0 && p.y < BY1) {
        // astype(int32) == trunc-toward-zero; coords are >= 0 here.
        int px = (int)__fdiv_rn(__fsub_rn(p.x, BX0), BRES);
        int py = (int)__fdiv_rn(__fsub_rn(p.y, BY0), BRES);
        px = min(max(px, 0), WID - 1);
        py = min(max(py, 0), HGT - 1);
        int idx = py * WID + px;

        atomicMax(&g_zmax[idx], enc_f(p.z));

        // fused count + intensity (16.16 fixed point) -> one 64-bit add
        unsigned long long fx = (unsigned long long)__float2uint_rn(p.w * 65536.0f);
        atomicAdd(&g_ic[idx], (1ull << 40) | fx);
    }
}

__global__ void finalize_kernel(float* __restrict__ out) {
    int i = blockIdx.x * blockDim.x + threadIdx.x;
    int stride = gridDim.x * blockDim.x;
    const float inv_log129 = 1.0f / logf(1.0f + 128.0f);
    for (int j = i; j < NPIX; j += stride) {
        unsigned long long ic = g_ic[j];
        unsigned int cnt = (unsigned int)(ic >> 40);
        float cntf = (float)cnt;
        float isum = (float)(ic & ((1ull << 40) - 1ull)) * (1.0f / 65536.0f);

        float hmax  = (cnt > 0u) ? dec_f(g_zmax[j]) : 0.0f;  // isneginf -> 0.0 path
        float h     = __saturatef((hmax - BZ0) / (BZ1 - BZ0));
        float imean = (cnt > 0u) ? (isum / cntf) : 0.0f;
        float ich   = __saturatef(imean * (1.0f / 255.0f));
        float dch   = __saturatef(log1pf(cntf) * inv_log129);

        out[0 * NPIX + j] = h;
        out[1 * NPIX + j] = ich;
        out[2 * NPIX + j] = dch;
    }
}

// One block per segment. Channel 3 = trajectory, channel 4 = osm (ego-frame).
__global__ void polyline_kernel(const float2* __restrict__ traj, int ntraj,
                                const float2* __restrict__ osm,  int nosm,
                                const float*  __restrict__ ego,
                                float* __restrict__ out) {
    int nseg_t = ntraj - 1;
    int seg = blockIdx.x;

    float Axw, Ayw, Bxw, Byw;  // world/ego coords of segment endpoints
    int ch;
    if (seg < nseg_t) {
        ch = 3;
        float2 a = traj[seg], b = traj[seg + 1];
        Axw = a.x; Ayw = a.y; Bxw = b.x; Byw = b.y;
    } else {
        ch = 4;
        int s = seg - nseg_t;
        float th = -ego[2];
        float cy = cosf(th), sy = sinf(th);
        float ex = ego[0], ey = ego[1];
        float2 a = osm[s], b = osm[s + 1];
        float dax = __fsub_rn(a.x, ex), day = __fsub_rn(a.y, ey);
        float dbx = __fsub_rn(b.x, ex), dby = __fsub_rn(b.y, ey);
        Axw = __fsub_rn(__fmul_rn(dax, cy), __fmul_rn(day, sy));
        Ayw = __fadd_rn(__fmul_rn(dax, sy), __fmul_rn(day, cy));
        Bxw = __fsub_rn(__fmul_rn(dbx, cy), __fmul_rn(dby, sy));
        Byw = __fadd_rn(__fmul_rn(dbx, sy), __fmul_rn(dby, cy));
    }

    // pixel coords: trunc((v - lo)/RES), IEEE div to match jnp f32 exactly
    float ax = truncf(__fdiv_rn(__fsub_rn(Axw, BX0), BRES));
    float ay = truncf(__fdiv_rn(__fsub_rn(Ayw, BY0), BRES));
    float bx = truncf(__fdiv_rn(__fsub_rn(Bxw, BX0), BRES));
    float by = truncf(__fdiv_rn(__fsub_rn(Byw, BY0), BRES));

    bool inA = (ax >= 0.0f) && (ax < (float)WID) && (ay >= 0.0f) && (ay < (float)HGT);
    bool inB = (bx >= 0.0f) && (bx < (float)WID) && (by >= 0.0f) && (by < (float)HGT);
    if (!(inA || inB)) return;  // valid==0 -> scatter-max of 0 is a no-op

    // clip to [0, W-1] x [0, H-1]
    ax = fminf(fmaxf(ax, 0.0f), (float)(WID - 1));
    bx = fminf(fmaxf(bx, 0.0f), (float)(WID - 1));
    ay = fminf(fmaxf(ay, 0.0f), (float)(HGT - 1));
    by = fminf(fmaxf(by, 0.0f), (float)(HGT - 1));

    float dx = __fsub_rn(bx, ax);
    float dy = __fsub_rn(by, ay);
    float dmax = fmaxf(fabsf(dx), fabsf(dy));
    float den  = fmaxf(dmax, 1.0f);

    // all k > ceil(dmax) clamp to the same pixel -> loop only to kmax
    int kmax = min(KSAMP - 1, (int)ceilf(dmax));

    float* o = out + ch * NPIX;
    for (int k = threadIdx.x; k <= kmax; k += blockDim.x) {
        float t = __fdiv_rn(fminf((float)k, dmax), den);
        // match jnp: a + t*(b-a), no FMA contraction
        float fx = __fadd_rn(ax, __fmul_rn(t, dx));
        float fy = __fadd_rn(ay, __fmul_rn(t, dy));
        int px = (int)rintf(fx);   // jnp.round = half-to-even = rintf
        int py = (int)rintf(fy);
        #pragma unroll
        for (int oy = -1; oy <= 1; oy++) {
            #pragma unroll
            for (int ox = -1; ox <= 1; ox++) {
                int x = px + ox, y = py + oy;
                // JAX .at[] semantics: negative indices wrap (NumPy style),
                // only idx >= dim is dropped. px,py >= 0, so only -1 occurs.
                if (x < 0) x += WID;
                if (y < 0) y += HGT;
                if (x < WID && y < HGT)
                    o[y * WID + x] = 1.0f;   // benign race: everyone writes 1.0
            }
        }
    }
}

// ---------------- launch ----------------
extern "C" void kernel_launch(void* const* d_in, const int* in_sizes, int n_in,
                              void* d_out, int out_size) {
    const float4* lidar = (const float4*)d_in[0];
    const float2* traj  = (const float2*)d_in[1];
    const float2* osm   = (const float2*)d_in[2];
    const float*  ego   = (const float*)d_in[3];
    float* out = (float*)d_out;

    int n     = in_sizes[0] / 4;
    int ntraj = in_sizes[1] / 2;
    int nosm  = in_sizes[2] / 2;
    int nseg  = (ntraj - 1) + (nosm - 1);

    init_kernel<<<296, 256>>>(out);
    lidar_kernel<<<(n + 255) / 256, 256>>>(lidar, n);
    polyline_kernel<<<nseg, 64>>>(traj, ntraj, osm, nosm, ego, out);
    finalize_kernel<<<296, 256>>>(out);
}

// round 6
// speedup vs baseline: 1.0758x; 1.0758x over previous
#include <cuda_runtime.h>
#include <cstdint>

// ---------------- problem constants ----------------
#define HGT 300
#define WID 400
#define NPIX (HGT * WID)
#define BX0 (-20.0f)
#define BX1 (20.0f)
#define BY0 (-10.0f)
#define BY1 (30.0f)
#define BZ0 (-3.0f)
#define BZ1 (4.0f)
#define BRES (0.1f)
#define KSAMP 512
#define R_IC 8   // replication factor for the count+intensity accumulator

// ---------------- scratch (no allocs allowed) ----------------
__device__ unsigned int g_zmax[NPIX];          // order-preserving float encoding of max z
__device__ unsigned int g_ic[R_IC][NPIX];      // [31:22]=count, [21:0]=intensity, x16 fixed

// order-preserving float<->uint map (monotone: f1<f2 <=> enc(f1)<enc(f2))
__device__ __forceinline__ unsigned int enc_f(float f) {
    unsigned int b = __float_as_uint(f);
    return (b & 0x80000000u) ? ~b : (b | 0x80000000u);
}
__device__ __forceinline__ float dec_f(unsigned int u) {
    unsigned int b = (u & 0x80000000u) ? (u ^ 0x80000000u) : ~u;
    return __uint_as_float(b);
}

// ---------------- kernels ----------------
__global__ void init_kernel(float* __restrict__ out) {
    int i = blockIdx.x * blockDim.x + threadIdx.x;
    int stride = gridDim.x * blockDim.x;
    for (int j = i; j < NPIX; j += stride) {
        g_zmax[j] = 0u;            // any real z encodes > 0; gated by count anyway
        #pragma unroll
        for (int r = 0; r < R_IC; r++) g_ic[r][j] = 0u;
        out[3 * NPIX + j] = 0.0f;  // trajectory channel
        out[4 * NPIX + j] = 0.0f;  // map channel
    }
}

__device__ __forceinline__ void lidar_point(float4 p, int rep) {
    // mask exactly as reference (on raw coords)
    if (p.x >= BX0 && p.x < BX1 && p.y >= BY0 && p.y < BY1) {
        // astype(int32) == trunc-toward-zero; coords are >= 0 here.
        int px = (int)__fdiv_rn(__fsub_rn(p.x, BX0), BRES);
        int py = (int)__fdiv_rn(__fsub_rn(p.y, BY0), BRES);
        px = min(max(px, 0), WID - 1);
        py = min(max(py, 0), HGT - 1);   // y in [20,30) all clips to row 299 (hot row!)
        int idx = py * WID + px;

        // z-max early-out: monotone max, stale (<=current) reads are safe.
        unsigned int e = enc_f(p.z);
        unsigned int cur = __ldcg(&g_zmax[idx]);
        if (e > cur) atomicMax(&g_zmax[idx], e);

        // fused count + intensity -> one 32-bit add, replicated.
        // count in [31:22] (<=1023), intensity sum in [21:0] at x16 scale:
        // worst hot cell ~1600 pts / 8 replicas = ~200 -> 200*255*16 ~ 0.8M << 2^22.
        unsigned int fx = __float2uint_rn(p.w * 16.0f);   // <= 4080
        atomicAdd(&g_ic[rep][idx], (1u << 22) | fx);
    }
}

__global__ void lidar_kernel(const float4* __restrict__ pts, int n) {
    int t = blockIdx.x * blockDim.x + threadIdx.x;
    int i0 = t * 2;
    int rep = (threadIdx.x + blockIdx.x) & (R_IC - 1);
    if (i0 + 1 < n) {
        // two independent loads -> overlapped latency
        float4 a = pts[i0];
        float4 b = pts[i0 + 1];
        lidar_point(a, rep);
        lidar_point(b, rep);
    } else if (i0 < n) {
        lidar_point(pts[i0], rep);
    }
}

__global__ void finalize_kernel(float* __restrict__ out) {
    int i = blockIdx.x * blockDim.x + threadIdx.x;
    int stride = gridDim.x * blockDim.x;
    const float inv_log129 = 1.0f / logf(1.0f + 128.0f);
    for (int j = i; j < NPIX; j += stride) {
        unsigned int cnt = 0u, ifx = 0u;
        #pragma unroll
        for (int r = 0; r < R_IC; r++) {
            unsigned int ic = g_ic[r][j];
            cnt += ic >> 22;
            ifx += ic & 0x3FFFFFu;
        }
        float cntf = (float)cnt;
        float isum = (float)ifx * (1.0f / 16.0f);

        float hmax  = (cnt > 0u) ? dec_f(g_zmax[j]) : 0.0f;  // isneginf -> 0.0 path
        float h     = __saturatef((hmax - BZ0) / (BZ1 - BZ0));
        float imean = (cnt > 0u) ? (isum / cntf) : 0.0f;
        float ich   = __saturatef(imean * (1.0f / 255.0f));
        float dch   = __saturatef(log1pf(cntf) * inv_log129);

        out[0 * NPIX + j] = h;
        out[1 * NPIX + j] = ich;
        out[2 * NPIX + j] = dch;
    }
}

// One block per segment. Channel 3 = trajectory, channel 4 = osm (ego-frame).
__global__ void polyline_kernel(const float2* __restrict__ traj, int ntraj,
                                const float2* __restrict__ osm,  int nosm,
                                const float*  __restrict__ ego,
                                float* __restrict__ out) {
    int nseg_t = ntraj - 1;
    int seg = blockIdx.x;

    float Axw, Ayw, Bxw, Byw;  // world/ego coords of segment endpoints
    int ch;
    if (seg < nseg_t) {
        ch = 3;
        float2 a = traj[seg], b = traj[seg + 1];
        Axw = a.x; Ayw = a.y; Bxw = b.x; Byw = b.y;
    } else {
        ch = 4;
        int s = seg - nseg_t;
        float th = -ego[2];
        float cy = cosf(th), sy = sinf(th);
        float ex = ego[0], ey = ego[1];
        float2 a = osm[s], b = osm[s + 1];
        float dax = __fsub_rn(a.x, ex), day = __fsub_rn(a.y, ey);
        float dbx = __fsub_rn(b.x, ex), dby = __fsub_rn(b.y, ey);
        Axw = __fsub_rn(__fmul_rn(dax, cy), __fmul_rn(day, sy));
        Ayw = __fadd_rn(__fmul_rn(dax, sy), __fmul_rn(day, cy));
        Bxw = __fsub_rn(__fmul_rn(dbx, cy), __fmul_rn(dby, sy));
        Byw = __fadd_rn(__fmul_rn(dbx, sy), __fmul_rn(dby, cy));
    }

    // pixel coords: trunc((v - lo)/RES), IEEE div to match jnp f32 exactly
    float ax = truncf(__fdiv_rn(__fsub_rn(Axw, BX0), BRES));
    float ay = truncf(__fdiv_rn(__fsub_rn(Ayw, BY0), BRES));
    float bx = truncf(__fdiv_rn(__fsub_rn(Bxw, BX0), BRES));
    float by = truncf(__fdiv_rn(__fsub_rn(Byw, BY0), BRES));

    bool inA = (ax >= 0.0f) && (ax < (float)WID) && (ay >= 0.0f) && (ay < (float)HGT);
    bool inB = (bx >= 0.0f) && (bx < (float)WID) && (by >= 0.0f) && (by < (float)HGT);
    if (!(inA || inB)) return;  // valid==0 -> scatter-max of 0 is a no-op

    // clip to [0, W-1] x [0, H-1]
    ax = fminf(fmaxf(ax, 0.0f), (float)(WID - 1));
    bx = fminf(fmaxf(bx, 0.0f), (float)(WID - 1));
    ay = fminf(fmaxf(ay, 0.0f), (float)(HGT - 1));
    by = fminf(fmaxf(by, 0.0f), (float)(HGT - 1));

    float dx = __fsub_rn(bx, ax);
    float dy = __fsub_rn(by, ay);
    float dmax = fmaxf(fabsf(dx), fabsf(dy));
    float den  = fmaxf(dmax, 1.0f);

    // all k > ceil(dmax) clamp to the same pixel -> loop only to kmax
    int kmax = min(KSAMP - 1, (int)ceilf(dmax));

    float* o = out + ch * NPIX;
    for (int k = threadIdx.x; k <= kmax; k += blockDim.x) {
        float t = __fdiv_rn(fminf((float)k, dmax), den);
        // match jnp: a + t*(b-a), no FMA contraction
        float fx = __fadd_rn(ax, __fmul_rn(t, dx));
        float fy = __fadd_rn(ay, __fmul_rn(t, dy));
        int px = (int)rintf(fx);   // jnp.round = half-to-even = rintf
        int py = (int)rintf(fy);
        #pragma unroll
        for (int oy = -1; oy <= 1; oy++) {
            #pragma unroll
            for (int ox = -1; ox <= 1; ox++) {
                int x = px + ox, y = py + oy;
                // JAX .at[] semantics: negative indices wrap (NumPy style),
                // only idx >= dim is dropped. px,py >= 0, so only -1 occurs.
                if (x < 0) x += WID;
                if (y < 0) y += HGT;
                if (x < WID && y < HGT)
                    o[y * WID + x] = 1.0f;   // benign race: everyone writes 1.0
            }
        }
    }
}

// ---------------- launch ----------------
extern "C" void kernel_launch(void* const* d_in, const int* in_sizes, int n_in,
                              void* d_out, int out_size) {
    const float4* lidar = (const float4*)d_in[0];
    const float2* traj  = (const float2*)d_in[1];
    const float2* osm   = (const float2*)d_in[2];
    const float*  ego   = (const float*)d_in[3];
    float* out = (float*)d_out;

    int n     = in_sizes[0] / 4;
    int ntraj = in_sizes[1] / 2;
    int nosm  = in_sizes[2] / 2;
    int nseg  = (ntraj - 1) + (nosm - 1);

    init_kernel<<<469, 256>>>(out);
    int nthreads = (n + 1) / 2;
    lidar_kernel<<<(nthreads + 255) / 256, 256>>>(lidar, n);
    polyline_kernel<<<nseg, 64>>>(traj, ntraj, osm, nosm, ego, out);
    finalize_kernel<<<469, 256>>>(out);
}

// round 7
// speedup vs baseline: 1.2925x; 1.2015x over previous
#include <cuda_runtime.h>
#include <cstdint>

// ---------------- problem constants ----------------
#define HGT 300
#define WID 400
#define NPIX (HGT * WID)
#define BX0 (-20.0f)
#define BX1 (20.0f)
#define BY0 (-10.0f)
#define BY1 (30.0f)
#define BZ0 (-3.0f)
#define BZ1 (4.0f)
#define BRES (0.1f)
#define KSAMP 512
#define R_IC 8   // replication factor for the count+intensity accumulator

// ---------------- scratch (no allocs; zero-initialized at module load) ----------
// finalize_kernel re-zeroes these after reading, so every kernel_launch call
// starts from zeroed state (deterministic across graph replays).
__device__ unsigned int g_zmax[NPIX];          // order-preserving float encoding of max z
__device__ unsigned int g_ic[R_IC][NPIX];      // [31:22]=count, [21:0]=intensity, x16 fixed

// order-preserving float<->uint map (monotone: f1<f2 <=> enc(f1)<enc(f2))
__device__ __forceinline__ unsigned int enc_f(float f) {
    unsigned int b = __float_as_uint(f);
    return (b & 0x80000000u) ? ~b : (b | 0x80000000u);
}
__device__ __forceinline__ float dec_f(unsigned int u) {
    unsigned int b = (u & 0x80000000u) ? (u ^ 0x80000000u) : ~u;
    return __uint_as_float(b);
}

// ---------------- kernels ----------------
__device__ __forceinline__ void lidar_point(float4 p, int rep) {
    // mask exactly as reference (on raw coords)
    if (p.x >= BX0 && p.x < BX1 && p.y >= BY0 && p.y < BY1) {
        // astype(int32) == trunc-toward-zero; coords are >= 0 here.
        int px = (int)__fdiv_rn(__fsub_rn(p.x, BX0), BRES);
        int py = (int)__fdiv_rn(__fsub_rn(p.y, BY0), BRES);
        px = min(max(px, 0), WID - 1);
        py = min(max(py, 0), HGT - 1);   // y in [20,30) all clips to row 299 (hot row)
        int idx = py * WID + px;

        // z-max early-out: monotone max, stale (<=current) reads are safe.
        unsigned int e = enc_f(p.z);
        unsigned int cur = __ldcg(&g_zmax[idx]);
        if (e > cur) atomicMax(&g_zmax[idx], e);

        // fused count + intensity -> one 32-bit add, replicated.
        // count [31:22] (<=1023/replica), intensity [21:0] x16:
        // worst hot cell ~1600 pts / 8 replicas -> 200*255*16 ~ 0.8M << 2^22.
        unsigned int fx = __float2uint_rn(p.w * 16.0f);
        atomicAdd(&g_ic[rep][idx], (1u << 22) | fx);
    }
}

// Processes points [base, base+count). If poly_out != nullptr, also zeroes the
// two polyline output channels (stream-ordered before polyline_kernel runs).
__global__ void lidar_kernel(const float4* __restrict__ pts, int base, int count,
                             float* __restrict__ poly_out) {
    int t = blockIdx.x * blockDim.x + threadIdx.x;
    if (poly_out && t < 2 * NPIX) poly_out[t] = 0.0f;

    int i0 = base + t * 2;
    int end = base + count;
    int rep = (threadIdx.x + blockIdx.x) & (R_IC - 1);
    if (i0 + 1 < end) {
        float4 a = pts[i0];
        float4 b = pts[i0 + 1];
        lidar_point(a, rep);
        lidar_point(b, rep);
    } else if (i0 < end) {
        lidar_point(pts[i0], rep);
    }
}

__global__ void finalize_kernel(float* __restrict__ out) {
    int i = blockIdx.x * blockDim.x + threadIdx.x;
    int stride = gridDim.x * blockDim.x;
    const float inv_log129 = 1.0f / logf(1.0f + 128.0f);
    for (int j = i; j < NPIX; j += stride) {
        unsigned int cnt = 0u, ifx = 0u;
        #pragma unroll
        for (int r = 0; r < R_IC; r++) {
            unsigned int ic = g_ic[r][j];
            cnt += ic >> 22;
            ifx += ic & 0x3FFFFFu;
        }
        float cntf = (float)cnt;
        float isum = (float)ifx * (1.0f / 16.0f);

        float hmax  = (cnt > 0u) ? dec_f(g_zmax[j]) : 0.0f;  // isneginf -> 0.0 path
        float h     = __saturatef((hmax - BZ0) / (BZ1 - BZ0));
        float imean = (cnt > 0u) ? (isum / cntf) : 0.0f;
        float ich   = __saturatef(imean * (1.0f / 255.0f));
        float dch   = __saturatef(log1pf(cntf) * inv_log129);

        out[0 * NPIX + j] = h;
        out[1 * NPIX + j] = ich;
        out[2 * NPIX + j] = dch;

        // self-clean for the next call / graph replay
        g_zmax[j] = 0u;
        #pragma unroll
        for (int r = 0; r < R_IC; r++) g_ic[r][j] = 0u;
    }
}

// One block per segment. Channel 3 = trajectory, channel 4 = osm (ego-frame).
__global__ void polyline_kernel(const float2* __restrict__ traj, int ntraj,
                                const float2* __restrict__ osm,  int nosm,
                                const float*  __restrict__ ego,
                                float* __restrict__ out) {
    int nseg_t = ntraj - 1;
    int seg = blockIdx.x;

    float Axw, Ayw, Bxw, Byw;  // world/ego coords of segment endpoints
    int ch;
    if (seg < nseg_t) {
        ch = 3;
        float2 a = traj[seg], b = traj[seg + 1];
        Axw = a.x; Ayw = a.y; Bxw = b.x; Byw = b.y;
    } else {
        ch = 4;
        int s = seg - nseg_t;
        float th = -ego[2];
        float cy = cosf(th), sy = sinf(th);
        float ex = ego[0], ey = ego[1];
        float2 a = osm[s], b = osm[s + 1];
        float dax = __fsub_rn(a.x, ex), day = __fsub_rn(a.y, ey);
        float dbx = __fsub_rn(b.x, ex), dby = __fsub_rn(b.y, ey);
        Axw = __fsub_rn(__fmul_rn(dax, cy), __fmul_rn(day, sy));
        Ayw = __fadd_rn(__fmul_rn(dax, sy), __fmul_rn(day, cy));
        Bxw = __fsub_rn(__fmul_rn(dbx, cy), __fmul_rn(dby, sy));
        Byw = __fadd_rn(__fmul_rn(dbx, sy), __fmul_rn(dby, cy));
    }

    // pixel coords: trunc((v - lo)/RES), IEEE div to match jnp f32 exactly
    float ax = truncf(__fdiv_rn(__fsub_rn(Axw, BX0), BRES));
    float ay = truncf(__fdiv_rn(__fsub_rn(Ayw, BY0), BRES));
    float bx = truncf(__fdiv_rn(__fsub_rn(Bxw, BX0), BRES));
    float by = truncf(__fdiv_rn(__fsub_rn(Byw, BY0), BRES));

    bool inA = (ax >= 0.0f) && (ax < (float)WID) && (ay >= 0.0f) && (ay < (float)HGT);
    bool inB = (bx >= 0.0f) && (bx < (float)WID) && (by >= 0.0f) && (by < (float)HGT);
    if (!(inA || inB)) return;  // valid==0 -> scatter-max of 0 is a no-op

    // clip to [0, W-1] x [0, H-1]
    ax = fminf(fmaxf(ax, 0.0f), (float)(WID - 1));
    bx = fminf(fmaxf(bx, 0.0f), (float)(WID - 1));
    ay = fminf(fmaxf(ay, 0.0f), (float)(HGT - 1));
    by = fminf(fmaxf(by, 0.0f), (float)(HGT - 1));

    float dx = __fsub_rn(bx, ax);
    float dy = __fsub_rn(by, ay);
    float dmax = fmaxf(fabsf(dx), fabsf(dy));
    float den  = fmaxf(dmax, 1.0f);

    // all k > ceil(dmax) clamp to the same pixel -> loop only to kmax
    int kmax = min(KSAMP - 1, (int)ceilf(dmax));

    float* o = out + ch * NPIX;
    for (int k = threadIdx.x; k <= kmax; k += blockDim.x) {
        float t = __fdiv_rn(fminf((float)k, dmax), den);
        // match jnp: a + t*(b-a), no FMA contraction
        float fx = __fadd_rn(ax, __fmul_rn(t, dx));
        float fy = __fadd_rn(ay, __fmul_rn(t, dy));
        int px = (int)rintf(fx);   // jnp.round = half-to-even = rintf
        int py = (int)rintf(fy);
        #pragma unroll
        for (int oy = -1; oy <= 1; oy++) {
            #pragma unroll
            for (int ox = -1; ox <= 1; ox++) {
                int x = px + ox, y = py + oy;
                // JAX .at[] semantics: negative indices wrap (NumPy style),
                // only idx >= dim is dropped. px,py >= 0, so only -1 occurs.
                if (x < 0) x += WID;
                if (y < 0) y += HGT;
                if (x < WID && y < HGT)
                    o[y * WID + x] = 1.0f;   // benign race: everyone writes 1.0
            }
        }
    }
}

// ---------------- launch ----------------
extern "C" void kernel_launch(void* const* d_in, const int* in_sizes, int n_in,
                              void* d_out, int out_size) {
    const float4* lidar = (const float4*)d_in[0];
    const float2* traj  = (const float2*)d_in[1];
    const float2* osm   = (const float2*)d_in[2];
    const float*  ego   = (const float*)d_in[3];
    float* out = (float*)d_out;

    int n     = in_sizes[0] / 4;
    int ntraj = in_sizes[1] / 2;
    int nosm  = in_sizes[2] / 2;
    int nseg  = (ntraj - 1) + (nosm - 1);

    // split lidar into two half launches (A also zeroes polyline channels)
    int halfA = ((n / 2) + 1) & ~1;          // even count for A
    int cntB  = n - halfA;

    int thA = (halfA + 1) / 2;
    int thB = (cntB + 1) / 2;
    // lidarA must have enough threads to zero 2*NPIX floats (240k); 1M threads: ok.
    lidar_kernel<<<(thA + 255) / 256, 256>>>(lidar, 0, halfA, out + 3 * NPIX);
    lidar_kernel<<<(thB + 255) / 256, 256>>>(lidar, halfA, cntB, nullptr);
    polyline_kernel<<<nseg, 64>>>(traj, ntraj, osm, nosm, ego, out);
    finalize_kernel<<<469, 256>>>(out);
}

// round 8
// speedup vs baseline: 3.5619x; 2.7559x over previous
#include <cuda_runtime.h>
#include <cstdint>

// ---------------- problem constants ----------------
#define HGT 300
#define WID 400
#define NPIX (HGT * WID)
#define BX0 (-20.0f)
#define BX1 (20.0f)
#define BY0 (-10.0f)
#define BY1 (30.0f)
#define BZ0 (-3.0f)
#define BZ1 (4.0f)
#define BRES (0.1f)
#define KSAMP 512

#define TPB 256
#define PTS_PER_THREAD 8
#define PTS_PER_BLOCK (TPB * PTS_PER_THREAD)

// ---------------- scratch (no allocs; zero-init at module load) ----------------
// finalize_kernel self-cleans these after reading -> deterministic per replay.
__device__ unsigned int       g_zmax[NPIX];  // order-preserving float encoding of max z
__device__ unsigned long long g_ic[NPIX];    // [63:40]=count, [39:0]=intensity x16 fixed

// order-preserving float<->uint map (monotone: f1<f2 <=> enc(f1)<enc(f2))
__device__ __forceinline__ unsigned int enc_f(float f) {
    unsigned int b = __float_as_uint(f);
    return (b & 0x80000000u) ? ~b : (b | 0x80000000u);
}
__device__ __forceinline__ float dec_f(unsigned int u) {
    unsigned int b = (u & 0x80000000u) ? (u ^ 0x80000000u) : ~u;
    return __uint_as_float(b);
}

// ---------------- lidar: SMEM-privatized hot row (299), global for the rest ----
__global__ void __launch_bounds__(TPB) lidar_kernel(const float4* __restrict__ pts, int n,
                                                    float* __restrict__ poly_out) {
    __shared__ unsigned int       s_zmax[WID];  // hot-row z max (encoded)
    __shared__ unsigned long long s_ic[WID];    // hot-row cnt|intensity

    int tid = threadIdx.x;
    for (int c = tid; c < WID; c += TPB) { s_zmax[c] = 0u; s_ic[c] = 0ull; }

    // zero the two polyline channels (stream-ordered before polyline_kernel)
    int gt = blockIdx.x * TPB + tid;
    for (int j = gt; j < 2 * NPIX; j += gridDim.x * TPB) poly_out[j] = 0.0f;

    __syncthreads();

    int base = blockIdx.x * PTS_PER_BLOCK;
    #pragma unroll
    for (int k = 0; k < PTS_PER_THREAD; k++) {
        int i = base + k * TPB + tid;          // coalesced within each iteration
        if (i >= n) break;
        float4 p = pts[i];
        // mask exactly as reference (raw coords)
        if (p.x >= BX0 && p.x < BX1 && p.y >= BY0 && p.y < BY1) {
            // astype(int32) trunc-toward-zero; coords >= 0 here
            int px = (int)__fdiv_rn(__fsub_rn(p.x, BX0), BRES);
            int py = (int)__fdiv_rn(__fsub_rn(p.y, BY0), BRES);
            px = min(max(px, 0), WID - 1);
            py = min(max(py, 0), HGT - 1);     // y in [19.9,30) all clips to row 299

            unsigned int e = enc_f(p.z);
            unsigned long long v =
                (1ull << 40) | (unsigned long long)__float2uint_rn(p.w * 16.0f);

            if (py == HGT - 1) {
                // hot row: cheap SMEM atomics, flushed coalesced below
                atomicMax(&s_zmax[px], e);
                atomicAdd(&s_ic[px], v);
            } else {
                int idx = py * WID + px;
                atomicMax(&g_zmax[idx], e);
                atomicAdd(&g_ic[idx], v);
            }
        }
    }

    __syncthreads();
    // coalesced flush of the hot row
    for (int c = tid; c < WID; c += TPB) {
        unsigned long long v = s_ic[c];
        if (v) {
            atomicAdd(&g_ic[(HGT - 1) * WID + c], v);
            atomicMax(&g_zmax[(HGT - 1) * WID + c], s_zmax[c]);
        }
    }
}

__global__ void finalize_kernel(float* __restrict__ out) {
    int i = blockIdx.x * blockDim.x + threadIdx.x;
    int stride = gridDim.x * blockDim.x;
    const float inv_log129 = 1.0f / logf(1.0f + 128.0f);
    for (int j = i; j < NPIX; j += stride) {
        unsigned long long ic = g_ic[j];
        unsigned int cnt = (unsigned int)(ic >> 40);
        float cntf = (float)cnt;
        float isum = (float)(ic & ((1ull << 40) - 1ull)) * (1.0f / 16.0f);

        float hmax  = (cnt > 0u) ? dec_f(g_zmax[j]) : 0.0f;  // isneginf -> 0.0 path
        float h     = __saturatef((hmax - BZ0) / (BZ1 - BZ0));
        float imean = (cnt > 0u) ? (isum / cntf) : 0.0f;
        float ich   = __saturatef(imean * (1.0f / 255.0f));
        float dch   = __saturatef(log1pf(cntf) * inv_log129);

        out[0 * NPIX + j] = h;
        out[1 * NPIX + j] = ich;
        out[2 * NPIX + j] = dch;

        // self-clean for the next call / graph replay
        g_zmax[j] = 0u;
        g_ic[j]   = 0ull;
    }
}

// One block per segment. Channel 3 = trajectory, channel 4 = osm (ego-frame).
__global__ void polyline_kernel(const float2* __restrict__ traj, int ntraj,
                                const float2* __restrict__ osm,  int nosm,
                                const float*  __restrict__ ego,
                                float* __restrict__ out) {
    int nseg_t = ntraj - 1;
    int seg = blockIdx.x;

    float Axw, Ayw, Bxw, Byw;
    int ch;
    if (seg < nseg_t) {
        ch = 3;
        float2 a = traj[seg], b = traj[seg + 1];
        Axw = a.x; Ayw = a.y; Bxw = b.x; Byw = b.y;
    } else {
        ch = 4;
        int s = seg - nseg_t;
        float th = -ego[2];
        float cy = cosf(th), sy = sinf(th);
        float ex = ego[0], ey = ego[1];
        float2 a = osm[s], b = osm[s + 1];
        float dax = __fsub_rn(a.x, ex), day = __fsub_rn(a.y, ey);
        float dbx = __fsub_rn(b.x, ex), dby = __fsub_rn(b.y, ey);
        Axw = __fsub_rn(__fmul_rn(dax, cy), __fmul_rn(day, sy));
        Ayw = __fadd_rn(__fmul_rn(dax, sy), __fmul_rn(day, cy));
        Bxw = __fsub_rn(__fmul_rn(dbx, cy), __fmul_rn(dby, sy));
        Byw = __fadd_rn(__fmul_rn(dbx, sy), __fmul_rn(dby, cy));
    }

    // pixel coords: trunc((v - lo)/RES), IEEE div to match jnp f32 exactly
    float ax = truncf(__fdiv_rn(__fsub_rn(Axw, BX0), BRES));
    float ay = truncf(__fdiv_rn(__fsub_rn(Ayw, BY0), BRES));
    float bx = truncf(__fdiv_rn(__fsub_rn(Bxw, BX0), BRES));
    float by = truncf(__fdiv_rn(__fsub_rn(Byw, BY0), BRES));

    bool inA = (ax >= 0.0f) && (ax < (float)WID) && (ay >= 0.0f) && (ay < (float)HGT);
    bool inB = (bx >= 0.0f) && (bx < (float)WID) && (by >= 0.0f) && (by < (float)HGT);
    if (!(inA || inB)) return;

    ax = fminf(fmaxf(ax, 0.0f), (float)(WID - 1));
    bx = fminf(fmaxf(bx, 0.0f), (float)(WID - 1));
    ay = fminf(fmaxf(ay, 0.0f), (float)(HGT - 1));
    by = fminf(fmaxf(by, 0.0f), (float)(HGT - 1));

    float dx = __fsub_rn(bx, ax);
    float dy = __fsub_rn(by, ay);
    float dmax = fmaxf(fabsf(dx), fabsf(dy));
    float den  = fmaxf(dmax, 1.0f);

    int kmax = min(KSAMP - 1, (int)ceilf(dmax));

    float* o = out + ch * NPIX;
    for (int k = threadIdx.x; k <= kmax; k += blockDim.x) {
        float t = __fdiv_rn(fminf((float)k, dmax), den);
        float fx = __fadd_rn(ax, __fmul_rn(t, dx));
        float fy = __fadd_rn(ay, __fmul_rn(t, dy));
        int px = (int)rintf(fx);   // jnp.round = half-to-even
        int py = (int)rintf(fy);
        #pragma unroll
        for (int oy = -1; oy <= 1; oy++) {
            #pragma unroll
            for (int ox = -1; ox <= 1; ox++) {
                int x = px + ox, y = py + oy;
                // JAX .at[]: negative indices wrap, >= dim drops. Only -1 occurs.
                if (x < 0) x += WID;
                if (y < 0) y += HGT;
                if (x < WID && y < HGT)
                    o[y * WID + x] = 1.0f;   // benign race
            }
        }
    }
}

// ---------------- launch ----------------
extern "C" void kernel_launch(void* const* d_in, const int* in_sizes, int n_in,
                              void* d_out, int out_size) {
    const float4* lidar = (const float4*)d_in[0];
    const float2* traj  = (const float2*)d_in[1];
    const float2* osm   = (const float2*)d_in[2];
    const float*  ego   = (const float*)d_in[3];
    float* out = (float*)d_out;

    int n     = in_sizes[0] / 4;
    int ntraj = in_sizes[1] / 2;
    int nosm  = in_sizes[2] / 2;
    int nseg  = (ntraj - 1) + (nosm - 1);

    int blocks = (n + PTS_PER_BLOCK - 1) / PTS_PER_BLOCK;
    lidar_kernel<<<blocks, TPB>>>(lidar, n, out + 3 * NPIX);
    polyline_kernel<<<nseg, 64>>>(traj, ntraj, osm, nosm, ego, out);
    finalize_kernel<<<469, 256>>>(out);
}